// round 1
// baseline (speedup 1.0000x reference)
#include <cuda_runtime.h>
#include <cuda_bf16.h>

// ---------------------------------------------------------------------------
// InfoNCELoss: fused normalize + (A@N^T -> exp -> rowsum) + (A@P^T -> loss)
// Round 0 baseline: fp32 SMEM-tiled GEMM, fused epilogues, fp64 accumulators.
// ---------------------------------------------------------------------------

#define DDIM 512
#define MAXB 4096
#define MAXP 4096
#define MAXN 16384

// Scratch (device globals; no allocations allowed in kernel_launch)
__device__ float g_An[(size_t)MAXB * DDIM];
__device__ float g_Pn[(size_t)MAXP * DDIM];
__device__ float g_Nn[(size_t)MAXN * DDIM];
__device__ float g_S[MAXB];           // per-anchor sum_k exp(neg_sim)
__device__ double g_sum_neg;          // sum of all neg_sim values
__device__ double g_sum_pos;          // sum of all pos_sim values
__device__ double g_sum_loss;         // sum of all per-pair losses

__global__ void zero_kernel() {
    int i = blockIdx.x * blockDim.x + threadIdx.x;
    if (i < MAXB) g_S[i] = 0.0f;
    if (i == 0) { g_sum_neg = 0.0; g_sum_pos = 0.0; g_sum_loss = 0.0; }
}

// One block per row; 128 threads, one float4 each (DDIM=512).
__global__ void normalize_kernel(const float* __restrict__ in, int which, int rows) {
    int row = blockIdx.x;
    if (row >= rows) return;
    float* out = (which == 0) ? g_An : (which == 1) ? g_Pn : g_Nn;

    const float4* src = (const float4*)in + (size_t)row * (DDIM / 4) + threadIdx.x;
    float4 v = *src;
    float ss = v.x * v.x + v.y * v.y + v.z * v.z + v.w * v.w;

    // warp butterfly
    #pragma unroll
    for (int off = 16; off; off >>= 1)
        ss += __shfl_xor_sync(0xffffffffu, ss, off);

    __shared__ float wsum[4];
    int warp = threadIdx.x >> 5;
    if ((threadIdx.x & 31) == 0) wsum[warp] = ss;
    __syncthreads();
    float tot = wsum[0] + wsum[1] + wsum[2] + wsum[3];
    float inv = 1.0f / fmaxf(sqrtf(tot), 1e-12f);

    float4 o;
    o.x = v.x * inv; o.y = v.y * inv; o.z = v.z * inv; o.w = v.w * inv;
    ((float4*)out)[(size_t)row * (DDIM / 4) + threadIdx.x] = o;
}

// ---------------------------------------------------------------------------
// GEMM: C[i,j] = dot(A_row_i, B_row_j) * (1/T), fused epilogue.
// MODE 0: B = g_Nn  -> g_S[i] += sum_j exp(sim); g_sum_neg += sum(sim)
// MODE 1: B = g_Pn  -> loss via g_S[i];         g_sum_pos  += sum(sim)
// Tiles: BM=BN=128, BK=16, 256 threads, 8x8 per-thread microtile.
// Dims are multiples of 128 (4096 / 16384) -> no bounds checks.
// ---------------------------------------------------------------------------
template <int MODE>
__global__ void __launch_bounds__(256, 2) gemm_kernel(int Mrows, int Ncols) {
    const float* __restrict__ A = g_An;
    const float* __restrict__ Bm = (MODE == 0) ? g_Nn : g_Pn;

    __shared__ float As[16][128];
    __shared__ float Bs[16][128];

    const int t = threadIdx.x;
    const int tx = t & 15;      // 0..15 -> col group
    const int ty = t >> 4;      // 0..15 -> row group
    const int rowBase = blockIdx.y * 128;
    const int colBase = blockIdx.x * 128;

    float acc[8][8];
    #pragma unroll
    for (int i = 0; i < 8; i++)
        #pragma unroll
        for (int j = 0; j < 8; j++) acc[i][j] = 0.0f;

    const float4* Ag = (const float4*)A + (size_t)rowBase * (DDIM / 4);
    const float4* Bg = (const float4*)Bm + (size_t)colBase * (DDIM / 4);

    for (int kt = 0; kt < DDIM / 16; ++kt) {
        #pragma unroll
        for (int l = 0; l < 2; ++l) {
            int f = t + l * 256;          // 0..511 : 128 rows x 4 float4
            int r = f >> 2;
            int c = f & 3;
            float4 va = Ag[(size_t)r * (DDIM / 4) + kt * 4 + c];
            As[c * 4 + 0][r] = va.x;
            As[c * 4 + 1][r] = va.y;
            As[c * 4 + 2][r] = va.z;
            As[c * 4 + 3][r] = va.w;
            float4 vb = Bg[(size_t)r * (DDIM / 4) + kt * 4 + c];
            Bs[c * 4 + 0][r] = vb.x;
            Bs[c * 4 + 1][r] = vb.y;
            Bs[c * 4 + 2][r] = vb.z;
            Bs[c * 4 + 3][r] = vb.w;
        }
        __syncthreads();

        #pragma unroll
        for (int k = 0; k < 16; ++k) {
            float a[8], b[8];
            *(float4*)&a[0] = *(const float4*)&As[k][ty * 8];
            *(float4*)&a[4] = *(const float4*)&As[k][ty * 8 + 4];
            *(float4*)&b[0] = *(const float4*)&Bs[k][tx * 8];
            *(float4*)&b[4] = *(const float4*)&Bs[k][tx * 8 + 4];
            #pragma unroll
            for (int i = 0; i < 8; i++)
                #pragma unroll
                for (int j = 0; j < 8; j++)
                    acc[i][j] = fmaf(a[i], b[j], acc[i][j]);
        }
        __syncthreads();
    }

    const float invT = 1.0f / 0.07f;

    if (MODE == 0) {
        // ---- neg epilogue: exp row-sum into g_S, fp64 sum of sims ----
        double dsum = 0.0;
        float rowexp[8];
        #pragma unroll
        for (int i = 0; i < 8; i++) rowexp[i] = 0.0f;
        #pragma unroll
        for (int i = 0; i < 8; i++)
            #pragma unroll
            for (int j = 0; j < 8; j++) {
                float s = acc[i][j] * invT;
                dsum += (double)s;
                rowexp[i] += __expf(s);
            }
        // reduce rowexp across the 16 tx lanes (butterfly within 16-lane group)
        #pragma unroll
        for (int off = 1; off < 16; off <<= 1)
            #pragma unroll
            for (int i = 0; i < 8; i++)
                rowexp[i] += __shfl_xor_sync(0xffffffffu, rowexp[i], off);
        if (tx == 0) {
            #pragma unroll
            for (int i = 0; i < 8; i++)
                atomicAdd(&g_S[rowBase + ty * 8 + i], rowexp[i]);
        }
        // block-reduce dsum -> one fp64 atomic per block
        #pragma unroll
        for (int off = 16; off; off >>= 1)
            dsum += __shfl_xor_sync(0xffffffffu, dsum, off);
        __shared__ double dred[8];
        int warp = t >> 5;
        if ((t & 31) == 0) dred[warp] = dsum;
        __syncthreads();
        if (t == 0) {
            double s = 0.0;
            #pragma unroll
            for (int w = 0; w < 8; w++) s += dred[w];
            atomicAdd(&g_sum_neg, s);
        }
    } else {
        // ---- pos epilogue: loss using g_S, fp64 sums ----
        float Sv[8];
        #pragma unroll
        for (int i = 0; i < 8; i++) Sv[i] = g_S[rowBase + ty * 8 + i];

        double dsum = 0.0, dloss = 0.0;
        #pragma unroll
        for (int i = 0; i < 8; i++)
            #pragma unroll
            for (int j = 0; j < 8; j++) {
                float s = acc[i][j] * invT;
                dsum += (double)s;
                float pe = __expf(s);
                float r = __fdividef(pe, pe + Sv[i]);
                dloss += (double)(-__logf(r + 1e-8f));
            }
        #pragma unroll
        for (int off = 16; off; off >>= 1) {
            dsum  += __shfl_xor_sync(0xffffffffu, dsum,  off);
            dloss += __shfl_xor_sync(0xffffffffu, dloss, off);
        }
        __shared__ double dredA[8], dredB[8];
        int warp = t >> 5;
        if ((t & 31) == 0) { dredA[warp] = dsum; dredB[warp] = dloss; }
        __syncthreads();
        if (t == 0) {
            double s = 0.0, l = 0.0;
            #pragma unroll
            for (int w = 0; w < 8; w++) { s += dredA[w]; l += dredB[w]; }
            atomicAdd(&g_sum_pos, s);
            atomicAdd(&g_sum_loss, l);
        }
    }
}

__global__ void finalize_kernel(float* __restrict__ out, int B, int P, int N) {
    if (threadIdx.x == 0 && blockIdx.x == 0) {
        double bp = (double)B * (double)P;
        double bn = (double)B * (double)N;
        float tl = (float)(g_sum_loss / bp);
        float mp = (float)(g_sum_pos / bp);
        float mn = (float)(g_sum_neg / bn);
        out[0] = tl;
        out[1] = mp;
        out[2] = mn;
        out[3] = mp - mn;
    }
}

extern "C" void kernel_launch(void* const* d_in, const int* in_sizes, int n_in,
                              void* d_out, int out_size) {
    const float* a = (const float*)d_in[0];
    const float* p = (const float*)d_in[1];
    const float* n = (const float*)d_in[2];
    int B = in_sizes[0] / DDIM;   // 4096
    int P = in_sizes[1] / DDIM;   // 4096
    int N = in_sizes[2] / DDIM;   // 16384

    zero_kernel<<<(MAXB + 255) / 256, 256>>>();
    normalize_kernel<<<B, 128>>>(a, 0, B);
    normalize_kernel<<<P, 128>>>(p, 1, P);
    normalize_kernel<<<N, 128>>>(n, 2, N);

    dim3 gridNeg(N / 128, B / 128);
    gemm_kernel<0><<<gridNeg, 256>>>(B, N);

    dim3 gridPos(P / 128, B / 128);
    gemm_kernel<1><<<gridPos, 256>>>(B, P);

    finalize_kernel<<<1, 32>>>((float*)d_out, B, P, N);
}

// round 3
// speedup vs baseline: 3.7299x; 3.7299x over previous
#include <cuda_runtime.h>
#include <cuda_bf16.h>
#include <stdint.h>

// ---------------------------------------------------------------------------
// InfoNCELoss on GB300 (plain sm_103 target -> legacy mma.sync tensor path)
//   normalize f32 -> {f32 copy (exact colsums), bf16 copy (MMA)}
//   mma<0>: A@N^T -> exp rowsum -> g_S      (fused epilogue)
//   mma<1>: A@P^T -> loss via g_S           (fused epilogue)
//   means from f32 colsums (exact), loss from bf16 GEMM (error ~1e-7 rel)
// ---------------------------------------------------------------------------

#define DDIM 512

// device scratch (no allocations allowed)
__device__ float    g_Anf[(size_t)4096  * DDIM];
__device__ float    g_Pnf[(size_t)4096  * DDIM];
__device__ float    g_Nnf[(size_t)16384 * DDIM];
__device__ uint32_t g_Anb[(size_t)4096  * 256];   // bf16x2 packed, 256 words/row
__device__ uint32_t g_Pnb[(size_t)4096  * 256];
__device__ uint32_t g_Nnb[(size_t)16384 * 256];
__device__ float    g_S[4096];
__device__ double   g_sum_loss;
__device__ double   g_cs[3][DDIM];

// ============================ PTX helpers ==================================
__device__ __forceinline__ uint32_t smem_to_u32(const void* p) {
    uint32_t a;
    asm("{ .reg .u64 t; cvta.to.shared.u64 t, %1; cvt.u32.u64 %0, t; }"
        : "=r"(a) : "l"(p));
    return a;
}
__device__ __forceinline__ void cp_async16(uint32_t dst, const void* src) {
    asm volatile("cp.async.cg.shared.global [%0], [%1], 16;" :: "r"(dst), "l"(src));
}
#define CP_COMMIT() asm volatile("cp.async.commit_group;" ::: "memory")
#define CP_WAIT(n)  asm volatile("cp.async.wait_group %0;" :: "n"(n) : "memory")

__device__ __forceinline__ void ldsm_x4(uint32_t (&r)[4], uint32_t addr) {
    asm volatile("ldmatrix.sync.aligned.m8n8.x4.shared.b16 {%0,%1,%2,%3}, [%4];"
                 : "=r"(r[0]), "=r"(r[1]), "=r"(r[2]), "=r"(r[3]) : "r"(addr));
}
__device__ __forceinline__ void mma16816(float (&c)[4], const uint32_t (&a)[4],
                                         uint32_t b0, uint32_t b1) {
    asm volatile(
        "mma.sync.aligned.m16n8k16.row.col.f32.bf16.bf16.f32 "
        "{%0,%1,%2,%3}, {%4,%5,%6,%7}, {%8,%9}, {%0,%1,%2,%3};"
        : "+f"(c[0]), "+f"(c[1]), "+f"(c[2]), "+f"(c[3])
        : "r"(a[0]), "r"(a[1]), "r"(a[2]), "r"(a[3]), "r"(b0), "r"(b1));
}

// ============================ small kernels ================================
__global__ void zero_kernel() {
    int i = blockIdx.x * blockDim.x + threadIdx.x;
    if (i < 4096) g_S[i] = 0.0f;
    if (i < 3 * DDIM) ((double*)g_cs)[i] = 0.0;
    if (i == 0) g_sum_loss = 0.0;
}

// one block per row; 128 threads
__global__ void __launch_bounds__(128) normalize_kernel(const float* __restrict__ in,
                                                        int which) {
    int row = blockIdx.x;
    float*    outf = (which == 0) ? g_Anf : (which == 1) ? g_Pnf : g_Nnf;
    uint32_t* outb = (which == 0) ? g_Anb : (which == 1) ? g_Pnb : g_Nnb;

    float4 v = ((const float4*)in)[(size_t)row * (DDIM / 4) + threadIdx.x];
    float ss = v.x * v.x + v.y * v.y + v.z * v.z + v.w * v.w;
    #pragma unroll
    for (int off = 16; off; off >>= 1)
        ss += __shfl_xor_sync(0xffffffffu, ss, off);
    __shared__ float wsum[4];
    int warp = threadIdx.x >> 5;
    if ((threadIdx.x & 31) == 0) wsum[warp] = ss;
    __syncthreads();
    float tot = wsum[0] + wsum[1] + wsum[2] + wsum[3];
    float inv = 1.0f / fmaxf(sqrtf(tot), 1e-12f);

    float4 o;
    o.x = v.x * inv; o.y = v.y * inv; o.z = v.z * inv; o.w = v.w * inv;
    ((float4*)outf)[(size_t)row * (DDIM / 4) + threadIdx.x] = o;

    __nv_bfloat162 w0 = __floats2bfloat162_rn(o.x, o.y);
    __nv_bfloat162 w1 = __floats2bfloat162_rn(o.z, o.w);
    outb[(size_t)row * 256 + threadIdx.x * 2 + 0] = *(uint32_t*)&w0;
    outb[(size_t)row * 256 + threadIdx.x * 2 + 1] = *(uint32_t*)&w1;
}

// exact colsums of f32 normalized matrices (for mean_pos / mean_neg)
__global__ void __launch_bounds__(512) colsum_kernel(int B, int P, int N) {
    int m = blockIdx.y;
    int rows = (m == 0) ? B : (m == 1) ? P : N;
    int base = blockIdx.x * 256;
    if (base >= rows) return;
    const float* M = (m == 0) ? g_Anf : (m == 1) ? g_Pnf : g_Nnf;
    int col = threadIdx.x;
    float acc = 0.0f;
    int lim = min(256, rows - base);
    for (int r = 0; r < lim; r++)
        acc += M[(size_t)(base + r) * DDIM + col];
    atomicAdd(&g_cs[m][col], (double)acc);
}

// ============================ MMA GEMM =====================================
// CTA tile 128(M) x 256(N), BK=32, K=512 (16 k-tiles), 8 warps (2Mx4N),
// warp tile 64x64. SMEM chunk-column-major: chunk(row,c) at (c*ROWS+row)*16B.
// MODE 0: B = g_Nnb -> exp rowsum into g_S
// MODE 1: B = g_Pnb -> loss via g_S into g_sum_loss
template <int MODE>
__global__ void __launch_bounds__(256, 1) mma_kernel() {
    __shared__ __align__(128) char sbuf[49152];   // As:2x8KB  Bs:2x16KB
    const uint32_t sb = smem_to_u32(sbuf);

    const int tid = threadIdx.x;
    const int lane = tid & 31;
    const int warp = tid >> 5;
    const int wm = warp >> 2;           // 0..1
    const int wn = warp & 3;            // 0..3
    const int m0 = wm * 64;
    const int n0 = wn * 64;
    const int rowBase = blockIdx.y * 128;
    const int colBase = blockIdx.x * 256;

    const char* gA = (const char*)g_Anb + (size_t)rowBase * 1024;
    const char* gB = (const char*)((MODE == 0) ? g_Nnb : g_Pnb) + (size_t)colBase * 1024;

    float c[4][8][4];
    #pragma unroll
    for (int i = 0; i < 4; i++)
        #pragma unroll
        for (int j = 0; j < 8; j++)
            #pragma unroll
            for (int e = 0; e < 4; e++) c[i][j][e] = 0.0f;

    // ---- async loaders (one commit group per k-tile) ----
    auto load_tile = [&](int kt, int stage) {
        uint32_t aBase = sb + stage * 8192;
        #pragma unroll
        for (int i = 0; i < 2; i++) {               // A: 512 chunks
            int id = tid + i * 256;
            int r = id & 127, cc = id >> 7;
            cp_async16(aBase + id * 16, gA + (size_t)r * 1024 + kt * 64 + cc * 16);
        }
        uint32_t bBase = sb + 16384 + stage * 16384;
        #pragma unroll
        for (int i = 0; i < 4; i++) {               // B: 1024 chunks
            int id = tid + i * 256;
            int n = id & 255, cc = id >> 8;
            cp_async16(bBase + id * 16, gB + (size_t)n * 1024 + kt * 64 + cc * 16);
        }
        CP_COMMIT();
    };

    load_tile(0, 0);

    for (int kt = 0; kt < 16; kt++) {
        if (kt + 1 < 16) load_tile(kt + 1, (kt + 1) & 1);
        if (kt + 1 < 16) { CP_WAIT(1); } else { CP_WAIT(0); }
        __syncthreads();

        uint32_t aB = sb + (kt & 1) * 8192;
        uint32_t bB = sb + 16384 + (kt & 1) * 16384;

        #pragma unroll
        for (int ks = 0; ks < 2; ks++) {
            uint32_t a[4][4];
            #pragma unroll
            for (int mf = 0; mf < 4; mf++) {
                int r = m0 + mf * 16 + (lane & 15);
                int cc = ks * 2 + (lane >> 4);
                ldsm_x4(a[mf], aB + (uint32_t)(cc * 128 + r) * 16);
            }
            uint32_t b[4][4];   // b[np] = {b0(2np), b1(2np), b0(2np+1), b1(2np+1)}
            #pragma unroll
            for (int np = 0; np < 4; np++) {
                int grp = lane >> 3;
                int n = n0 + np * 16 + ((grp >> 1) ? 8 : 0) + (lane & 7);
                int cc = ks * 2 + (grp & 1);
                ldsm_x4(b[np], bB + (uint32_t)(cc * 256 + n) * 16);
            }
            #pragma unroll
            for (int mf = 0; mf < 4; mf++)
                #pragma unroll
                for (int nf = 0; nf < 8; nf++)
                    mma16816(c[mf][nf], a[mf],
                             b[nf >> 1][(nf & 1) * 2], b[nf >> 1][(nf & 1) * 2 + 1]);
        }
        __syncthreads();
    }

    // ---- fused epilogue ----
    const float invT = 1.0f / 0.07f;
    const int gID = lane >> 2;   // row within frag

    if (MODE == 0) {
        #pragma unroll
        for (int mf = 0; mf < 4; mf++) {
            float rs0 = 0.0f, rs1 = 0.0f;
            #pragma unroll
            for (int nf = 0; nf < 8; nf++) {
                rs0 += __expf(c[mf][nf][0] * invT) + __expf(c[mf][nf][1] * invT);
                rs1 += __expf(c[mf][nf][2] * invT) + __expf(c[mf][nf][3] * invT);
            }
            rs0 += __shfl_xor_sync(0xffffffffu, rs0, 1);
            rs0 += __shfl_xor_sync(0xffffffffu, rs0, 2);
            rs1 += __shfl_xor_sync(0xffffffffu, rs1, 1);
            rs1 += __shfl_xor_sync(0xffffffffu, rs1, 2);
            if ((lane & 3) == 0) {
                int row = rowBase + m0 + mf * 16 + gID;
                atomicAdd(&g_S[row], rs0);
                atomicAdd(&g_S[row + 8], rs1);
            }
        }
    } else {
        float lsum = 0.0f;
        #pragma unroll
        for (int mf = 0; mf < 4; mf++) {
            int row = rowBase + m0 + mf * 16 + gID;
            float S0 = g_S[row];
            float S1 = g_S[row + 8];
            #pragma unroll
            for (int nf = 0; nf < 8; nf++) {
                float p0 = __expf(c[mf][nf][0] * invT);
                float p1 = __expf(c[mf][nf][1] * invT);
                float p2 = __expf(c[mf][nf][2] * invT);
                float p3 = __expf(c[mf][nf][3] * invT);
                lsum += __logf(__fdividef(p0, p0 + S0) + 1e-8f);
                lsum += __logf(__fdividef(p1, p1 + S0) + 1e-8f);
                lsum += __logf(__fdividef(p2, p2 + S1) + 1e-8f);
                lsum += __logf(__fdividef(p3, p3 + S1) + 1e-8f);
            }
        }
        double acc = -(double)lsum;
        #pragma unroll
        for (int off = 16; off; off >>= 1)
            acc += __shfl_xor_sync(0xffffffffu, acc, off);
        __shared__ double red[8];
        if (lane == 0) red[warp] = acc;
        __syncthreads();
        if (tid == 0) {
            double s = 0.0;
            #pragma unroll
            for (int w = 0; w < 8; w++) s += red[w];
            atomicAdd(&g_sum_loss, s);
        }
    }
}

__global__ void finalize_kernel(float* __restrict__ out, int B, int P, int N) {
    if (threadIdx.x == 0 && blockIdx.x == 0) {
        double dAP = 0.0, dAN = 0.0;
        for (int d = 0; d < DDIM; d++) {
            dAP += g_cs[0][d] * g_cs[1][d];
            dAN += g_cs[0][d] * g_cs[2][d];
        }
        const double T = 0.07;
        double mp = dAP / ((double)B * (double)P * T);
        double mn = dAN / ((double)B * (double)N * T);
        double tl = g_sum_loss / ((double)B * (double)P);
        out[0] = (float)tl;
        out[1] = (float)mp;
        out[2] = (float)mn;
        out[3] = (float)(mp - mn);
    }
}

// ============================ launch =======================================
extern "C" void kernel_launch(void* const* d_in, const int* in_sizes, int n_in,
                              void* d_out, int out_size) {
    const float* a = (const float*)d_in[0];
    const float* p = (const float*)d_in[1];
    const float* n = (const float*)d_in[2];
    int B = in_sizes[0] / DDIM;   // 4096
    int P = in_sizes[1] / DDIM;   // 4096
    int N = in_sizes[2] / DDIM;   // 16384

    zero_kernel<<<16, 256>>>();
    normalize_kernel<<<B, 128>>>(a, 0);
    normalize_kernel<<<P, 128>>>(p, 1);
    normalize_kernel<<<N, 128>>>(n, 2);

    dim3 csGrid(N / 256, 3);
    colsum_kernel<<<csGrid, 512>>>(B, P, N);

    dim3 gridNeg(N / 256, B / 128);
    mma_kernel<0><<<gridNeg, 256>>>();

    dim3 gridPos(P / 256, B / 128);
    mma_kernel<1><<<gridPos, 256>>>();

    finalize_kernel<<<1, 32>>>((float*)d_out, B, P, N);
}

// round 4
// speedup vs baseline: 4.1541x; 1.1137x over previous
#include <cuda_runtime.h>
#include <cuda_bf16.h>
#include <stdint.h>

// ---------------------------------------------------------------------------
// InfoNCELoss on GB300 (sm_103 target -> legacy mma.sync bf16 tensor path)
//   normalize f32 -> {f32 copy (exact colsums), bf16 copy (MMA)}
//   mma<0>: A@N^T -> exp rowsum -> g_S      (fused epilogue)
//   mma<1>: A@P^T -> loss via g_S           (fused epilogue)
//   means from f32 colsums (exact), loss from bf16 GEMM
// R4: 128-thr CTAs (2/SM), 3-stage cp.async pipeline, frag double-buffering.
// ---------------------------------------------------------------------------

#define DDIM 512

__device__ float    g_Anf[(size_t)4096  * DDIM];
__device__ float    g_Pnf[(size_t)4096  * DDIM];
__device__ float    g_Nnf[(size_t)16384 * DDIM];
__device__ uint32_t g_Anb[(size_t)4096  * 256];   // bf16x2 packed, 256 words/row
__device__ uint32_t g_Pnb[(size_t)4096  * 256];
__device__ uint32_t g_Nnb[(size_t)16384 * 256];
__device__ float    g_S[4096];
__device__ double   g_sum_loss;
__device__ double   g_cs[3][DDIM];

// ============================ PTX helpers ==================================
__device__ __forceinline__ uint32_t smem_to_u32(const void* p) {
    uint32_t a;
    asm("{ .reg .u64 t; cvta.to.shared.u64 t, %1; cvt.u32.u64 %0, t; }"
        : "=r"(a) : "l"(p));
    return a;
}
__device__ __forceinline__ void cp_async16(uint32_t dst, const void* src) {
    asm volatile("cp.async.cg.shared.global [%0], [%1], 16;" :: "r"(dst), "l"(src));
}
#define CP_COMMIT() asm volatile("cp.async.commit_group;" ::: "memory")
#define CP_WAIT(n)  asm volatile("cp.async.wait_group %0;" :: "n"(n) : "memory")

__device__ __forceinline__ void ldsm_x4(uint32_t (&r)[4], uint32_t addr) {
    asm volatile("ldmatrix.sync.aligned.m8n8.x4.shared.b16 {%0,%1,%2,%3}, [%4];"
                 : "=r"(r[0]), "=r"(r[1]), "=r"(r[2]), "=r"(r[3]) : "r"(addr));
}
__device__ __forceinline__ void mma16816(float (&c)[4], const uint32_t (&a)[4],
                                         uint32_t b0, uint32_t b1) {
    asm volatile(
        "mma.sync.aligned.m16n8k16.row.col.f32.bf16.bf16.f32 "
        "{%0,%1,%2,%3}, {%4,%5,%6,%7}, {%8,%9}, {%0,%1,%2,%3};"
        : "+f"(c[0]), "+f"(c[1]), "+f"(c[2]), "+f"(c[3])
        : "r"(a[0]), "r"(a[1]), "r"(a[2]), "r"(a[3]), "r"(b0), "r"(b1));
}

// ============================ small kernels ================================
__global__ void zero_kernel() {
    int i = blockIdx.x * blockDim.x + threadIdx.x;
    if (i < 4096) g_S[i] = 0.0f;
    if (i < 3 * DDIM) ((double*)g_cs)[i] = 0.0;
    if (i == 0) g_sum_loss = 0.0;
}

__global__ void __launch_bounds__(128) normalize_kernel(const float* __restrict__ in,
                                                        int which) {
    int row = blockIdx.x;
    float*    outf = (which == 0) ? g_Anf : (which == 1) ? g_Pnf : g_Nnf;
    uint32_t* outb = (which == 0) ? g_Anb : (which == 1) ? g_Pnb : g_Nnb;

    float4 v = ((const float4*)in)[(size_t)row * (DDIM / 4) + threadIdx.x];
    float ss = v.x * v.x + v.y * v.y + v.z * v.z + v.w * v.w;
    #pragma unroll
    for (int off = 16; off; off >>= 1)
        ss += __shfl_xor_sync(0xffffffffu, ss, off);
    __shared__ float wsum[4];
    int warp = threadIdx.x >> 5;
    if ((threadIdx.x & 31) == 0) wsum[warp] = ss;
    __syncthreads();
    float tot = wsum[0] + wsum[1] + wsum[2] + wsum[3];
    float inv = 1.0f / fmaxf(sqrtf(tot), 1e-12f);

    float4 o;
    o.x = v.x * inv; o.y = v.y * inv; o.z = v.z * inv; o.w = v.w * inv;
    ((float4*)outf)[(size_t)row * (DDIM / 4) + threadIdx.x] = o;

    __nv_bfloat162 w0 = __floats2bfloat162_rn(o.x, o.y);
    __nv_bfloat162 w1 = __floats2bfloat162_rn(o.z, o.w);
    outb[(size_t)row * 256 + threadIdx.x * 2 + 0] = *(uint32_t*)&w0;
    outb[(size_t)row * 256 + threadIdx.x * 2 + 1] = *(uint32_t*)&w1;
}

__global__ void __launch_bounds__(512) colsum_kernel(int B, int P, int N) {
    int m = blockIdx.y;
    int rows = (m == 0) ? B : (m == 1) ? P : N;
    int base = blockIdx.x * 256;
    if (base >= rows) return;
    const float* M = (m == 0) ? g_Anf : (m == 1) ? g_Pnf : g_Nnf;
    int col = threadIdx.x;
    float acc = 0.0f;
    int lim = min(256, rows - base);
    for (int r = 0; r < lim; r++)
        acc += M[(size_t)(base + r) * DDIM + col];
    atomicAdd(&g_cs[m][col], (double)acc);
}

// ============================ MMA GEMM =====================================
// CTA: 128 threads (4 warps, 2Mx2N), tile 128x128, BK=32, K=512 -> 16 k-tiles.
// 3-stage cp.async pipeline; per-stage smem: A 8KB + B 8KB. Frag dbl-buffer.
// SMEM chunk layout per stage: chunk (row r, 16B-chunk cc) at (cc*128+r)*16.
#define STAGE_BYTES 16384

template <int MODE>
__global__ void __launch_bounds__(128, 2) mma_kernel() {
    __shared__ __align__(128) char sbuf[3 * STAGE_BYTES];   // 48KB
    const uint32_t sb = smem_to_u32(sbuf);

    const int tid = threadIdx.x;
    const int lane = tid & 31;
    const int warp = tid >> 5;
    const int m0 = (warp >> 1) * 64;
    const int n0 = (warp & 1) * 64;
    const int rowBase = blockIdx.y * 128;
    const int colBase = blockIdx.x * 128;

    const char* gA = (const char*)g_Anb + (size_t)rowBase * 1024;
    const char* gB = (const char*)((MODE == 0) ? g_Nnb : g_Pnb) + (size_t)colBase * 1024;

    float c[4][8][4];
    #pragma unroll
    for (int i = 0; i < 4; i++)
        #pragma unroll
        for (int j = 0; j < 8; j++)
            #pragma unroll
            for (int e = 0; e < 4; e++) c[i][j][e] = 0.0f;

    // ---- stage loader: A 512 chunks + B 512 chunks, 16B each ----
    auto load_tile = [&](int kt, int stage) {
        uint32_t base = sb + stage * STAGE_BYTES;
        #pragma unroll
        for (int i = 0; i < 4; i++) {
            int id = tid + i * 128;
            int r = id & 127, cc = id >> 7;          // cc 0..3
            cp_async16(base + (uint32_t)id * 16,
                       gA + (size_t)r * 1024 + kt * 64 + cc * 16);
        }
        #pragma unroll
        for (int i = 0; i < 4; i++) {
            int id = tid + i * 128;
            int n = id & 127, cc = id >> 7;
            cp_async16(base + 8192 + (uint32_t)id * 16,
                       gB + (size_t)n * 1024 + kt * 64 + cc * 16);
        }
    };

    // ---- fragment loader for one k16 step (ks in 0..1) ----
    auto load_frags = [&](int stage, int ks, uint32_t (&a)[4][4], uint32_t (&b)[4][4]) {
        uint32_t aB = sb + stage * STAGE_BYTES;
        uint32_t bB = aB + 8192;
        #pragma unroll
        for (int mf = 0; mf < 4; mf++) {
            int r = m0 + mf * 16 + (lane & 15);
            int cc = ks * 2 + (lane >> 4);
            ldsm_x4(a[mf], aB + (uint32_t)(cc * 128 + r) * 16);
        }
        #pragma unroll
        for (int np = 0; np < 4; np++) {
            int grp = lane >> 3;
            int n = n0 + np * 16 + ((grp >> 1) ? 8 : 0) + (lane & 7);
            int cc = ks * 2 + (grp & 1);
            ldsm_x4(b[np], bB + (uint32_t)(cc * 128 + n) * 16);
        }
    };

    auto mma_all = [&](const uint32_t (&a)[4][4], const uint32_t (&b)[4][4]) {
        #pragma unroll
        for (int mf = 0; mf < 4; mf++)
            #pragma unroll
            for (int nf = 0; nf < 8; nf++)
                mma16816(c[mf][nf], a[mf],
                         b[nf >> 1][(nf & 1) * 2], b[nf >> 1][(nf & 1) * 2 + 1]);
    };

    // ---- prologue: prefetch 2 stages ----
    load_tile(0, 0); CP_COMMIT();
    load_tile(1, 1); CP_COMMIT();

    uint32_t a2[2][4][4], b2[2][4][4];

    for (int kt = 0; kt < 16; kt++) {
        CP_WAIT(1);
        __syncthreads();
        int st = kt % 3;

        load_frags(st, 0, a2[0], b2[0]);
        if (kt + 2 < 16) load_tile(kt + 2, (kt + 2) % 3);
        CP_COMMIT();                       // commit (possibly empty) group
        load_frags(st, 1, a2[1], b2[1]);
        mma_all(a2[0], b2[0]);
        mma_all(a2[1], b2[1]);
    }

    // ---- fused epilogue ----
    const float invT = 1.0f / 0.07f;
    const int gID = lane >> 2;

    if (MODE == 0) {
        #pragma unroll
        for (int mf = 0; mf < 4; mf++) {
            float rs0 = 0.0f, rs1 = 0.0f;
            #pragma unroll
            for (int nf = 0; nf < 8; nf++) {
                rs0 += __expf(c[mf][nf][0] * invT) + __expf(c[mf][nf][1] * invT);
                rs1 += __expf(c[mf][nf][2] * invT) + __expf(c[mf][nf][3] * invT);
            }
            rs0 += __shfl_xor_sync(0xffffffffu, rs0, 1);
            rs0 += __shfl_xor_sync(0xffffffffu, rs0, 2);
            rs1 += __shfl_xor_sync(0xffffffffu, rs1, 1);
            rs1 += __shfl_xor_sync(0xffffffffu, rs1, 2);
            if ((lane & 3) == 0) {
                int row = rowBase + m0 + mf * 16 + gID;
                atomicAdd(&g_S[row], rs0);
                atomicAdd(&g_S[row + 8], rs1);
            }
        }
    } else {
        float lsum = 0.0f;
        #pragma unroll
        for (int mf = 0; mf < 4; mf++) {
            int row = rowBase + m0 + mf * 16 + gID;
            float S0 = g_S[row];
            float S1 = g_S[row + 8];
            #pragma unroll
            for (int nf = 0; nf < 8; nf++) {
                float p0 = __expf(c[mf][nf][0] * invT);
                float p1 = __expf(c[mf][nf][1] * invT);
                float p2 = __expf(c[mf][nf][2] * invT);
                float p3 = __expf(c[mf][nf][3] * invT);
                lsum += __logf(__fdividef(p0, p0 + S0) + 1e-8f);
                lsum += __logf(__fdividef(p1, p1 + S0) + 1e-8f);
                lsum += __logf(__fdividef(p2, p2 + S1) + 1e-8f);
                lsum += __logf(__fdividef(p3, p3 + S1) + 1e-8f);
            }
        }
        double acc = -(double)lsum;
        #pragma unroll
        for (int off = 16; off; off >>= 1)
            acc += __shfl_xor_sync(0xffffffffu, acc, off);
        __shared__ double red[4];
        if (lane == 0) red[warp] = acc;
        __syncthreads();
        if (tid == 0)
            atomicAdd(&g_sum_loss, red[0] + red[1] + red[2] + red[3]);
    }
}

__global__ void finalize_kernel(float* __restrict__ out, int B, int P, int N) {
    if (threadIdx.x == 0 && blockIdx.x == 0) {
        double dAP = 0.0, dAN = 0.0;
        for (int d = 0; d < DDIM; d++) {
            dAP += g_cs[0][d] * g_cs[1][d];
            dAN += g_cs[0][d] * g_cs[2][d];
        }
        const double T = 0.07;
        double mp = dAP / ((double)B * (double)P * T);
        double mn = dAN / ((double)B * (double)N * T);
        double tl = g_sum_loss / ((double)B * (double)P);
        out[0] = (float)tl;
        out[1] = (float)mp;
        out[2] = (float)mn;
        out[3] = (float)(mp - mn);
    }
}

// ============================ launch =======================================
extern "C" void kernel_launch(void* const* d_in, const int* in_sizes, int n_in,
                              void* d_out, int out_size) {
    const float* a = (const float*)d_in[0];
    const float* p = (const float*)d_in[1];
    const float* n = (const float*)d_in[2];
    int B = in_sizes[0] / DDIM;   // 4096
    int P = in_sizes[1] / DDIM;   // 4096
    int N = in_sizes[2] / DDIM;   // 16384

    zero_kernel<<<16, 256>>>();
    normalize_kernel<<<B, 128>>>(a, 0);
    normalize_kernel<<<P, 128>>>(p, 1);
    normalize_kernel<<<N, 128>>>(n, 2);

    dim3 csGrid(N / 256, 3);
    colsum_kernel<<<csGrid, 512>>>(B, P, N);

    dim3 gridNeg(N / 128, B / 128);     // 128 x 32
    mma_kernel<0><<<gridNeg, 128>>>();

    dim3 gridPos(P / 128, B / 128);     // 32 x 32
    mma_kernel<1><<<gridPos, 128>>>();

    finalize_kernel<<<1, 32>>>((float*)d_out, B, P, N);
}

// round 5
// speedup vs baseline: 5.0819x; 1.2234x over previous
#include <cuda_runtime.h>
#include <cuda_bf16.h>
#include <cuda_fp8.h>
#include <stdint.h>

// ---------------------------------------------------------------------------
// InfoNCELoss on GB300 (sm_103 -> legacy mma.sync path, FP8 e4m3 m16n8k32)
//   normalize f32 -> {f32 copy (exact colsums), fp8 x32 copy (MMA)}
//   mma<0>: A@N^T -> exp rowsum -> g_S      (fused epilogue)
//   mma<1>: A@P^T -> loss via g_S           (fused epilogue)
//   means from f32 colsums (exact); loss via fp8 GEMM (bias cancels in ratio)
// ---------------------------------------------------------------------------

#define DDIM 512
#define FP8_SCALE 32.0f

__device__ float    g_Anf[(size_t)4096  * DDIM];
__device__ float    g_Pnf[(size_t)4096  * DDIM];
__device__ float    g_Nnf[(size_t)16384 * DDIM];
__device__ uint32_t g_Anq[(size_t)4096  * 128];   // e4m3 x4 packed, 128 words/row
__device__ uint32_t g_Pnq[(size_t)4096  * 128];
__device__ uint32_t g_Nnq[(size_t)16384 * 128];
__device__ float    g_S[4096];
__device__ double   g_sum_loss;
__device__ double   g_cs[3][DDIM];

// ============================ PTX helpers ==================================
__device__ __forceinline__ uint32_t smem_to_u32(const void* p) {
    uint32_t a;
    asm("{ .reg .u64 t; cvta.to.shared.u64 t, %1; cvt.u32.u64 %0, t; }"
        : "=r"(a) : "l"(p));
    return a;
}
__device__ __forceinline__ void cp_async16(uint32_t dst, const void* src) {
    asm volatile("cp.async.cg.shared.global [%0], [%1], 16;" :: "r"(dst), "l"(src));
}
#define CP_COMMIT() asm volatile("cp.async.commit_group;" ::: "memory")
#define CP_WAIT(n)  asm volatile("cp.async.wait_group %0;" :: "n"(n) : "memory")

__device__ __forceinline__ void ldsm_x4(uint32_t (&r)[4], uint32_t addr) {
    asm volatile("ldmatrix.sync.aligned.m8n8.x4.shared.b16 {%0,%1,%2,%3}, [%4];"
                 : "=r"(r[0]), "=r"(r[1]), "=r"(r[2]), "=r"(r[3]) : "r"(addr));
}
// FP8 e4m3 MMA, K=32 per instruction
__device__ __forceinline__ void mma16832(float (&c)[4], const uint32_t (&a)[4],
                                         uint32_t b0, uint32_t b1) {
    asm volatile(
        "mma.sync.aligned.m16n8k32.row.col.f32.e4m3.e4m3.f32 "
        "{%0,%1,%2,%3}, {%4,%5,%6,%7}, {%8,%9}, {%0,%1,%2,%3};"
        : "+f"(c[0]), "+f"(c[1]), "+f"(c[2]), "+f"(c[3])
        : "r"(a[0]), "r"(a[1]), "r"(a[2]), "r"(a[3]), "r"(b0), "r"(b1));
}

// ============================ small kernels ================================
__global__ void zero_kernel() {
    int i = blockIdx.x * blockDim.x + threadIdx.x;
    if (i < 4096) g_S[i] = 0.0f;
    if (i < 3 * DDIM) ((double*)g_cs)[i] = 0.0;
    if (i == 0) g_sum_loss = 0.0;
}

__global__ void __launch_bounds__(128) normalize_kernel(const float* __restrict__ in,
                                                        int which) {
    int row = blockIdx.x;
    float*    outf = (which == 0) ? g_Anf : (which == 1) ? g_Pnf : g_Nnf;
    uint32_t* outq = (which == 0) ? g_Anq : (which == 1) ? g_Pnq : g_Nnq;

    float4 v = ((const float4*)in)[(size_t)row * (DDIM / 4) + threadIdx.x];
    float ss = v.x * v.x + v.y * v.y + v.z * v.z + v.w * v.w;
    #pragma unroll
    for (int off = 16; off; off >>= 1)
        ss += __shfl_xor_sync(0xffffffffu, ss, off);
    __shared__ float wsum[4];
    int warp = threadIdx.x >> 5;
    if ((threadIdx.x & 31) == 0) wsum[warp] = ss;
    __syncthreads();
    float tot = wsum[0] + wsum[1] + wsum[2] + wsum[3];
    float inv = 1.0f / fmaxf(sqrtf(tot), 1e-12f);

    float4 o;
    o.x = v.x * inv; o.y = v.y * inv; o.z = v.z * inv; o.w = v.w * inv;
    ((float4*)outf)[(size_t)row * (DDIM / 4) + threadIdx.x] = o;

    // pack 4 scaled e4m3 into one word
    __nv_fp8x2_storage_t lo = __nv_cvt_float2_to_fp8x2(
        make_float2(o.x * FP8_SCALE, o.y * FP8_SCALE), __NV_SATFINITE, __NV_E4M3);
    __nv_fp8x2_storage_t hi = __nv_cvt_float2_to_fp8x2(
        make_float2(o.z * FP8_SCALE, o.w * FP8_SCALE), __NV_SATFINITE, __NV_E4M3);
    outq[(size_t)row * 128 + threadIdx.x] = (uint32_t)lo | ((uint32_t)hi << 16);
}

__global__ void __launch_bounds__(512) colsum_kernel(int B, int P, int N) {
    int m = blockIdx.y;
    int rows = (m == 0) ? B : (m == 1) ? P : N;
    int base = blockIdx.x * 256;
    if (base >= rows) return;
    const float* M = (m == 0) ? g_Anf : (m == 1) ? g_Pnf : g_Nnf;
    int col = threadIdx.x;
    float acc = 0.0f;
    int lim = min(256, rows - base);
    for (int r = 0; r < lim; r++)
        acc += M[(size_t)(base + r) * DDIM + col];
    atomicAdd(&g_cs[m][col], (double)acc);
}

// ============================ FP8 MMA GEMM =================================
// CTA: 128 threads (4 warps, 2Mx2N), tile 128x128, BK=64 fp8 bytes,
// K=512 -> 8 k-tiles. 3-stage cp.async pipeline; per-stage A 8KB + B 8KB.
// SMEM: 16B chunk (row r, chunk cc in 0..3) at (cc*128 + r)*16.
// FP8 m16n8k32 fragments are byte-isomorphic to bf16 m16n8k16 -> same ldsm.
#define STAGE_BYTES 16384

template <int MODE>
__global__ void __launch_bounds__(128, 2) mma_kernel() {
    __shared__ __align__(128) char sbuf[3 * STAGE_BYTES];   // 48KB
    const uint32_t sb = smem_to_u32(sbuf);

    const int tid = threadIdx.x;
    const int lane = tid & 31;
    const int warp = tid >> 5;
    const int m0 = (warp >> 1) * 64;
    const int n0 = (warp & 1) * 64;
    const int rowBase = blockIdx.y * 128;
    const int colBase = blockIdx.x * 128;

    const char* gA = (const char*)g_Anq + (size_t)rowBase * 512;
    const char* gB = (const char*)((MODE == 0) ? g_Nnq : g_Pnq) + (size_t)colBase * 512;

    float c[4][8][4];
    #pragma unroll
    for (int i = 0; i < 4; i++)
        #pragma unroll
        for (int j = 0; j < 8; j++)
            #pragma unroll
            for (int e = 0; e < 4; e++) c[i][j][e] = 0.0f;

    // ---- stage loader: A 512 chunks + B 512 chunks, 16B each ----
    auto load_tile = [&](int kt, int stage) {
        uint32_t base = sb + stage * STAGE_BYTES;
        #pragma unroll
        for (int i = 0; i < 4; i++) {
            int id = tid + i * 128;
            int r = id & 127, cc = id >> 7;          // cc 0..3
            cp_async16(base + (uint32_t)id * 16,
                       gA + (size_t)r * 512 + kt * 64 + cc * 16);
        }
        #pragma unroll
        for (int i = 0; i < 4; i++) {
            int id = tid + i * 128;
            int n = id & 127, cc = id >> 7;
            cp_async16(base + 8192 + (uint32_t)id * 16,
                       gB + (size_t)n * 512 + kt * 64 + cc * 16);
        }
    };

    // ---- fragment loader for one k32 step (ks in 0..1) ----
    auto load_frags = [&](int stage, int ks, uint32_t (&a)[4][4], uint32_t (&b)[4][4]) {
        uint32_t aB = sb + stage * STAGE_BYTES;
        uint32_t bB = aB + 8192;
        #pragma unroll
        for (int mf = 0; mf < 4; mf++) {
            int r = m0 + mf * 16 + (lane & 15);
            int cc = ks * 2 + (lane >> 4);
            ldsm_x4(a[mf], aB + (uint32_t)(cc * 128 + r) * 16);
        }
        #pragma unroll
        for (int np = 0; np < 4; np++) {
            int grp = lane >> 3;
            int n = n0 + np * 16 + ((grp >> 1) ? 8 : 0) + (lane & 7);
            int cc = ks * 2 + (grp & 1);
            ldsm_x4(b[np], bB + (uint32_t)(cc * 128 + n) * 16);
        }
    };

    auto mma_all = [&](const uint32_t (&a)[4][4], const uint32_t (&b)[4][4]) {
        #pragma unroll
        for (int mf = 0; mf < 4; mf++)
            #pragma unroll
            for (int nf = 0; nf < 8; nf++)
                mma16832(c[mf][nf], a[mf],
                         b[nf >> 1][(nf & 1) * 2], b[nf >> 1][(nf & 1) * 2 + 1]);
    };

    // ---- prologue: prefetch 2 stages ----
    load_tile(0, 0); CP_COMMIT();
    load_tile(1, 1); CP_COMMIT();

    uint32_t a2[2][4][4], b2[2][4][4];

    for (int kt = 0; kt < 8; kt++) {
        CP_WAIT(1);
        __syncthreads();
        int st = kt % 3;

        load_frags(st, 0, a2[0], b2[0]);
        if (kt + 2 < 8) load_tile(kt + 2, (kt + 2) % 3);
        CP_COMMIT();
        load_frags(st, 1, a2[1], b2[1]);
        mma_all(a2[0], b2[0]);
        mma_all(a2[1], b2[1]);
    }

    // ---- fused epilogue (accumulator = SCALE^2 * dot) ----
    const float invT = 1.0f / (0.07f * FP8_SCALE * FP8_SCALE);
    const int gID = lane >> 2;

    if (MODE == 0) {
        #pragma unroll
        for (int mf = 0; mf < 4; mf++) {
            float rs0 = 0.0f, rs1 = 0.0f;
            #pragma unroll
            for (int nf = 0; nf < 8; nf++) {
                rs0 += __expf(c[mf][nf][0] * invT) + __expf(c[mf][nf][1] * invT);
                rs1 += __expf(c[mf][nf][2] * invT) + __expf(c[mf][nf][3] * invT);
            }
            rs0 += __shfl_xor_sync(0xffffffffu, rs0, 1);
            rs0 += __shfl_xor_sync(0xffffffffu, rs0, 2);
            rs1 += __shfl_xor_sync(0xffffffffu, rs1, 1);
            rs1 += __shfl_xor_sync(0xffffffffu, rs1, 2);
            if ((lane & 3) == 0) {
                int row = rowBase + m0 + mf * 16 + gID;
                atomicAdd(&g_S[row], rs0);
                atomicAdd(&g_S[row + 8], rs1);
            }
        }
    } else {
        float lsum = 0.0f;
        #pragma unroll
        for (int mf = 0; mf < 4; mf++) {
            int row = rowBase + m0 + mf * 16 + gID;
            float S0 = g_S[row];
            float S1 = g_S[row + 8];
            #pragma unroll
            for (int nf = 0; nf < 8; nf++) {
                float p0 = __expf(c[mf][nf][0] * invT);
                float p1 = __expf(c[mf][nf][1] * invT);
                float p2 = __expf(c[mf][nf][2] * invT);
                float p3 = __expf(c[mf][nf][3] * invT);
                lsum += __logf(__fdividef(p0, p0 + S0) + 1e-8f);
                lsum += __logf(__fdividef(p1, p1 + S0) + 1e-8f);
                lsum += __logf(__fdividef(p2, p2 + S1) + 1e-8f);
                lsum += __logf(__fdividef(p3, p3 + S1) + 1e-8f);
            }
        }
        double acc = -(double)lsum;
        #pragma unroll
        for (int off = 16; off; off >>= 1)
            acc += __shfl_xor_sync(0xffffffffu, acc, off);
        __shared__ double red[4];
        if (lane == 0) red[warp] = acc;
        __syncthreads();
        if (tid == 0)
            atomicAdd(&g_sum_loss, red[0] + red[1] + red[2] + red[3]);
    }
}

__global__ void finalize_kernel(float* __restrict__ out, int B, int P, int N) {
    if (threadIdx.x == 0 && blockIdx.x == 0) {
        double dAP = 0.0, dAN = 0.0;
        for (int d = 0; d < DDIM; d++) {
            dAP += g_cs[0][d] * g_cs[1][d];
            dAN += g_cs[0][d] * g_cs[2][d];
        }
        const double T = 0.07;
        double mp = dAP / ((double)B * (double)P * T);
        double mn = dAN / ((double)B * (double)N * T);
        double tl = g_sum_loss / ((double)B * (double)P);
        out[0] = (float)tl;
        out[1] = (float)mp;
        out[2] = (float)mn;
        out[3] = (float)(mp - mn);
    }
}

// ============================ launch =======================================
extern "C" void kernel_launch(void* const* d_in, const int* in_sizes, int n_in,
                              void* d_out, int out_size) {
    const float* a = (const float*)d_in[0];
    const float* p = (const float*)d_in[1];
    const float* n = (const float*)d_in[2];
    int B = in_sizes[0] / DDIM;   // 4096
    int P = in_sizes[1] / DDIM;   // 4096
    int N = in_sizes[2] / DDIM;   // 16384

    zero_kernel<<<16, 256>>>();
    normalize_kernel<<<B, 128>>>(a, 0);
    normalize_kernel<<<P, 128>>>(p, 1);
    normalize_kernel<<<N, 128>>>(n, 2);

    dim3 csGrid(N / 256, 3);
    colsum_kernel<<<csGrid, 512>>>(B, P, N);

    dim3 gridNeg(N / 128, B / 128);     // 128 x 32
    mma_kernel<0><<<gridNeg, 128>>>();

    dim3 gridPos(P / 128, B / 128);     // 32 x 32
    mma_kernel<1><<<gridPos, 128>>>();

    finalize_kernel<<<1, 32>>>((float*)d_out, B, P, N);
}

// round 6
// speedup vs baseline: 5.7987x; 1.1410x over previous
#include <cuda_runtime.h>
#include <cuda_bf16.h>
#include <cuda_fp8.h>
#include <stdint.h>

// ---------------------------------------------------------------------------
// InfoNCELoss on GB300 (sm_103 legacy mma.sync path, FP8 e4m3 m16n8k32)
// R6: cp.async.bulk + mbarrier tile loads (kills 33M LDGSTS), tiled+swizzled
//     fp8 global layout written by normalize.
//   mma<0>: A@N^T -> exp rowsum -> g_S      (fused epilogue)
//   mma<1>: A@P^T -> loss via g_S           (fused epilogue)
//   means from f32 colsums (exact); loss via fp8 GEMM (bias cancels in ratio)
// ---------------------------------------------------------------------------

#define DDIM 512
#define FP8_SCALE 32.0f

__device__ float    g_Anf[(size_t)4096  * DDIM];
__device__ float    g_Pnf[(size_t)4096  * DDIM];
__device__ float    g_Nnf[(size_t)16384 * DDIM];
// fp8 matrices, TILED layout: [panel(128r)][kt(8)][r(128)][64B], swizzled chunks
__device__ __align__(1024) uint32_t g_Anq[(size_t)4096  * 128];
__device__ __align__(1024) uint32_t g_Pnq[(size_t)4096  * 128];
__device__ __align__(1024) uint32_t g_Nnq[(size_t)16384 * 128];
__device__ float    g_S[4096];
__device__ double   g_sum_loss;
__device__ double   g_cs[3][DDIM];

// ============================ PTX helpers ==================================
__device__ __forceinline__ uint32_t smem_to_u32(const void* p) {
    uint32_t a;
    asm("{ .reg .u64 t; cvta.to.shared.u64 t, %1; cvt.u32.u64 %0, t; }"
        : "=r"(a) : "l"(p));
    return a;
}
__device__ __forceinline__ void bulk_cp(uint32_t dst, const void* src,
                                        uint32_t bytes, uint32_t mbar) {
    asm volatile(
        "cp.async.bulk.shared::cta.global.mbarrier::complete_tx::bytes "
        "[%0], [%1], %2, [%3];"
        :: "r"(dst), "l"(src), "r"(bytes), "r"(mbar) : "memory");
}
#define MBARRIER_INIT(mbar, count) \
    asm volatile("mbarrier.init.shared.b64 [%0], %1;" \
        :: "r"((uint32_t)(mbar)), "r"((uint32_t)(count)) : "memory")
#define MBARRIER_EXPECT_TX(mbar, bytes) \
    asm volatile("mbarrier.arrive.expect_tx.shared.b64 _, [%0], %1;" \
        :: "r"((uint32_t)(mbar)), "r"((uint32_t)(bytes)) : "memory")
#define MBARRIER_WAIT_PARITY(mbar_smem_addr, phase_parity) do { \
    uint32_t _mbar = (uint32_t)(mbar_smem_addr); \
    uint32_t _parity = (uint32_t)(phase_parity); \
    uint32_t _done; \
    asm volatile( \
        "{\n\t.reg .pred p;\n\t" \
        "mbarrier.try_wait.parity.acquire.cta.shared::cta.b64 p, [%1], %2;\n\t" \
        "selp.b32 %0, 1, 0, p;\n\t}" \
        : "=r"(_done) : "r"(_mbar), "r"(_parity) : "memory"); \
    if (!_done) { \
        asm volatile( \
            "{\n\t.reg .pred P1;\n\t" \
            "WAIT_LOOP_%=:\n\t" \
            "mbarrier.try_wait.parity.acquire.cta.shared::cta.b64 P1, [%0], %1, 0x989680;\n\t" \
            "@P1 bra.uni WAIT_DONE_%=;\n\t" \
            "bra.uni WAIT_LOOP_%=;\n\t" \
            "WAIT_DONE_%=:\n\t}" \
            :: "r"(_mbar), "r"(_parity) : "memory"); \
    } \
} while (0)

__device__ __forceinline__ void ldsm_x4(uint32_t (&r)[4], uint32_t addr) {
    asm volatile("ldmatrix.sync.aligned.m8n8.x4.shared.b16 {%0,%1,%2,%3}, [%4];"
                 : "=r"(r[0]), "=r"(r[1]), "=r"(r[2]), "=r"(r[3]) : "r"(addr));
}
__device__ __forceinline__ void mma16832(float (&c)[4], const uint32_t (&a)[4],
                                         uint32_t b0, uint32_t b1) {
    asm volatile(
        "mma.sync.aligned.m16n8k32.row.col.f32.e4m3.e4m3.f32 "
        "{%0,%1,%2,%3}, {%4,%5,%6,%7}, {%8,%9}, {%0,%1,%2,%3};"
        : "+f"(c[0]), "+f"(c[1]), "+f"(c[2]), "+f"(c[3])
        : "r"(a[0]), "r"(a[1]), "r"(a[2]), "r"(a[3]), "r"(b0), "r"(b1));
}

// ============================ small kernels ================================
__global__ void zero_kernel() {
    int i = blockIdx.x * blockDim.x + threadIdx.x;
    if (i < 4096) g_S[i] = 0.0f;
    if (i < 3 * DDIM) ((double*)g_cs)[i] = 0.0;
    if (i == 0) g_sum_loss = 0.0;
}

__global__ void __launch_bounds__(128) normalize_kernel(const float* __restrict__ in,
                                                        int which) {
    int row = blockIdx.x;
    float*    outf = (which == 0) ? g_Anf : (which == 1) ? g_Pnf : g_Nnf;
    uint32_t* outq = (which == 0) ? g_Anq : (which == 1) ? g_Pnq : g_Nnq;

    int t = threadIdx.x;
    float4 v = ((const float4*)in)[(size_t)row * (DDIM / 4) + t];
    float ss = v.x * v.x + v.y * v.y + v.z * v.z + v.w * v.w;
    #pragma unroll
    for (int off = 16; off; off >>= 1)
        ss += __shfl_xor_sync(0xffffffffu, ss, off);
    __shared__ float wsum[4];
    int warp = t >> 5;
    if ((t & 31) == 0) wsum[warp] = ss;
    __syncthreads();
    float tot = wsum[0] + wsum[1] + wsum[2] + wsum[3];
    float inv = 1.0f / fmaxf(sqrtf(tot), 1e-12f);

    float4 o;
    o.x = v.x * inv; o.y = v.y * inv; o.z = v.z * inv; o.w = v.w * inv;
    ((float4*)outf)[(size_t)row * (DDIM / 4) + t] = o;

    __nv_fp8x2_storage_t lo = __nv_cvt_float2_to_fp8x2(
        make_float2(o.x * FP8_SCALE, o.y * FP8_SCALE), __NV_SATFINITE, __NV_E4M3);
    __nv_fp8x2_storage_t hi = __nv_cvt_float2_to_fp8x2(
        make_float2(o.z * FP8_SCALE, o.w * FP8_SCALE), __NV_SATFINITE, __NV_E4M3);
    uint32_t packed = (uint32_t)lo | ((uint32_t)hi << 16);

    // tiled + swizzled store: word index within panel:
    //   kt = t>>4 (64B chunk of the row), cc = (t>>2)&3, w = t&3
    uint32_t r = (uint32_t)row & 127;
    uint32_t panel = (uint32_t)row >> 7;
    uint32_t kt = (uint32_t)t >> 4;
    uint32_t cc = ((uint32_t)t >> 2) & 3;
    uint32_t w = (uint32_t)t & 3;
    uint32_t sw = cc ^ ((r >> 1) & 3);
    outq[(size_t)panel * 16384 + kt * 2048 + r * 16 + sw * 4 + w] = packed;
}

__global__ void __launch_bounds__(512) colsum_kernel(int B, int P, int N) {
    int m = blockIdx.y;
    int rows = (m == 0) ? B : (m == 1) ? P : N;
    int base = blockIdx.x * 256;
    if (base >= rows) return;
    const float* M = (m == 0) ? g_Anf : (m == 1) ? g_Pnf : g_Nnf;
    int col = threadIdx.x;
    float acc = 0.0f;
    int lim = min(256, rows - base);
    for (int r = 0; r < lim; r++)
        acc += M[(size_t)(base + r) * DDIM + col];
    atomicAdd(&g_cs[m][col], (double)acc);
}

// ============================ FP8 MMA GEMM =================================
// CTA: 128 threads (4 warps, 2Mx2N), tile 128x128, BK=64B, 8 k-tiles.
// 3-slot cp.async.bulk pipeline (2 bulk copies / tile), mbarrier ring.
// SMEM per slot: A 8KB + B 8KB, layout [r][4 chunks x16B], chunk swizzled.
#define STAGE_BYTES 16384

template <int MODE>
__global__ void __launch_bounds__(128, 2) mma_kernel() {
    __shared__ __align__(128) char sbuf[3 * STAGE_BYTES];   // 48KB
    __shared__ __align__(8) uint64_t mbars[3];
    const uint32_t sb = smem_to_u32(sbuf);
    const uint32_t mb = smem_to_u32(mbars);

    const int tid = threadIdx.x;
    const int lane = tid & 31;
    const int warp = tid >> 5;
    const int m0 = (warp >> 1) * 64;
    const int n0 = (warp & 1) * 64;
    const int rowBase = blockIdx.y * 128;
    const int colBase = blockIdx.x * 128;

    // tiled panels: 65536 bytes per 128-row panel, 8192 per k-tile
    const char* gA = (const char*)g_Anq + (size_t)(rowBase >> 7) * 65536;
    const char* gB = (const char*)((MODE == 0) ? g_Nnq : g_Pnq)
                     + (size_t)(colBase >> 7) * 65536;

    float c[4][8][4];
    #pragma unroll
    for (int i = 0; i < 4; i++)
        #pragma unroll
        for (int j = 0; j < 8; j++)
            #pragma unroll
            for (int e = 0; e < 4; e++) c[i][j][e] = 0.0f;

    if (tid == 0) {
        #pragma unroll
        for (int s = 0; s < 3; s++) MBARRIER_INIT(mb + s * 8, 1);
    }
    __syncthreads();

    // prologue: tiles 0,1,2 into slots 0,1,2
    if (tid == 0) {
        #pragma unroll
        for (int s = 0; s < 3; s++) {
            MBARRIER_EXPECT_TX(mb + s * 8, STAGE_BYTES);
            bulk_cp(sb + s * STAGE_BYTES,        gA + (size_t)s * 8192, 8192, mb + s * 8);
            bulk_cp(sb + s * STAGE_BYTES + 8192, gB + (size_t)s * 8192, 8192, mb + s * 8);
        }
    }

    auto load_frags = [&](int slot, int ks, uint32_t (&a)[4][4], uint32_t (&b)[4][4]) {
        uint32_t aB = sb + slot * STAGE_BYTES;
        uint32_t bB = aB + 8192;
        #pragma unroll
        for (int mf = 0; mf < 4; mf++) {
            uint32_t r = m0 + mf * 16 + (lane & 15);
            uint32_t cc = ks * 2 + (lane >> 4);
            uint32_t idx = r * 4 + (cc ^ ((r >> 1) & 3));
            ldsm_x4(a[mf], aB + idx * 16);
        }
        #pragma unroll
        for (int np = 0; np < 4; np++) {
            uint32_t grp = lane >> 3;
            uint32_t n = n0 + np * 16 + ((grp >> 1) ? 8 : 0) + (lane & 7);
            uint32_t cc = ks * 2 + (grp & 1);
            uint32_t idx = n * 4 + (cc ^ ((n >> 1) & 3));
            ldsm_x4(b[np], bB + idx * 16);
        }
    };
    auto mma_all = [&](const uint32_t (&a)[4][4], const uint32_t (&b)[4][4]) {
        #pragma unroll
        for (int mf = 0; mf < 4; mf++)
            #pragma unroll
            for (int nf = 0; nf < 8; nf++)
                mma16832(c[mf][nf], a[mf],
                         b[nf >> 1][(nf & 1) * 2], b[nf >> 1][(nf & 1) * 2 + 1]);
    };

    uint32_t a2[2][4][4], b2[2][4][4];

    for (int kt = 0; kt < 8; kt++) {
        int slot = kt % 3;
        MBARRIER_WAIT_PARITY(mb + slot * 8, (kt / 3) & 1);

        load_frags(slot, 0, a2[0], b2[0]);
        load_frags(slot, 1, a2[1], b2[1]);
        mma_all(a2[0], b2[0]);
        mma_all(a2[1], b2[1]);

        __syncthreads();      // all warps done with this slot
        if (tid == 0 && kt + 3 < 8) {
            int nt = kt + 3;
            MBARRIER_EXPECT_TX(mb + slot * 8, STAGE_BYTES);
            bulk_cp(sb + slot * STAGE_BYTES,        gA + (size_t)nt * 8192, 8192, mb + slot * 8);
            bulk_cp(sb + slot * STAGE_BYTES + 8192, gB + (size_t)nt * 8192, 8192, mb + slot * 8);
        }
    }

    // ---- fused epilogue (accumulator = SCALE^2 * dot) ----
    const float invT = 1.0f / (0.07f * FP8_SCALE * FP8_SCALE);
    const int gID = lane >> 2;

    if (MODE == 0) {
        #pragma unroll
        for (int mf = 0; mf < 4; mf++) {
            float rs0 = 0.0f, rs1 = 0.0f;
            #pragma unroll
            for (int nf = 0; nf < 8; nf++) {
                rs0 += __expf(c[mf][nf][0] * invT) + __expf(c[mf][nf][1] * invT);
                rs1 += __expf(c[mf][nf][2] * invT) + __expf(c[mf][nf][3] * invT);
            }
            rs0 += __shfl_xor_sync(0xffffffffu, rs0, 1);
            rs0 += __shfl_xor_sync(0xffffffffu, rs0, 2);
            rs1 += __shfl_xor_sync(0xffffffffu, rs1, 1);
            rs1 += __shfl_xor_sync(0xffffffffu, rs1, 2);
            if ((lane & 3) == 0) {
                int row = rowBase + m0 + mf * 16 + gID;
                atomicAdd(&g_S[row], rs0);
                atomicAdd(&g_S[row + 8], rs1);
            }
        }
    } else {
        float lsum = 0.0f;
        #pragma unroll
        for (int mf = 0; mf < 4; mf++) {
            int row = rowBase + m0 + mf * 16 + gID;
            float S0 = g_S[row];
            float S1 = g_S[row + 8];
            #pragma unroll
            for (int nf = 0; nf < 8; nf++) {
                float p0 = __expf(c[mf][nf][0] * invT);
                float p1 = __expf(c[mf][nf][1] * invT);
                float p2 = __expf(c[mf][nf][2] * invT);
                float p3 = __expf(c[mf][nf][3] * invT);
                lsum += __logf(__fdividef(p0, p0 + S0) + 1e-8f);
                lsum += __logf(__fdividef(p1, p1 + S0) + 1e-8f);
                lsum += __logf(__fdividef(p2, p2 + S1) + 1e-8f);
                lsum += __logf(__fdividef(p3, p3 + S1) + 1e-8f);
            }
        }
        double acc = -(double)lsum;
        #pragma unroll
        for (int off = 16; off; off >>= 1)
            acc += __shfl_xor_sync(0xffffffffu, acc, off);
        __shared__ double red[4];
        if (lane == 0) red[warp] = acc;
        __syncthreads();
        if (tid == 0)
            atomicAdd(&g_sum_loss, red[0] + red[1] + red[2] + red[3]);
    }
}

__global__ void finalize_kernel(float* __restrict__ out, int B, int P, int N) {
    if (threadIdx.x == 0 && blockIdx.x == 0) {
        double dAP = 0.0, dAN = 0.0;
        for (int d = 0; d < DDIM; d++) {
            dAP += g_cs[0][d] * g_cs[1][d];
            dAN += g_cs[0][d] * g_cs[2][d];
        }
        const double T = 0.07;
        double mp = dAP / ((double)B * (double)P * T);
        double mn = dAN / ((double)B * (double)N * T);
        double tl = g_sum_loss / ((double)B * (double)P);
        out[0] = (float)tl;
        out[1] = (float)mp;
        out[2] = (float)mn;
        out[3] = (float)(mp - mn);
    }
}

// ============================ launch =======================================
extern "C" void kernel_launch(void* const* d_in, const int* in_sizes, int n_in,
                              void* d_out, int out_size) {
    const float* a = (const float*)d_in[0];
    const float* p = (const float*)d_in[1];
    const float* n = (const float*)d_in[2];
    int B = in_sizes[0] / DDIM;   // 4096
    int P = in_sizes[1] / DDIM;   // 4096
    int N = in_sizes[2] / DDIM;   // 16384

    zero_kernel<<<16, 256>>>();
    normalize_kernel<<<B, 128>>>(a, 0);
    normalize_kernel<<<P, 128>>>(p, 1);
    normalize_kernel<<<N, 128>>>(n, 2);

    dim3 csGrid(N / 256, 3);
    colsum_kernel<<<csGrid, 512>>>(B, P, N);

    dim3 gridNeg(N / 128, B / 128);     // 128 x 32
    mma_kernel<0><<<gridNeg, 128>>>();

    dim3 gridPos(P / 128, B / 128);     // 32 x 32
    mma_kernel<1><<<gridPos, 128>>>();

    finalize_kernel<<<1, 32>>>((float*)d_out, B, P, N);
}